// round 17
// baseline (speedup 1.0000x reference)
#include <cuda_runtime.h>

#define IMG 512
#define TW 64
#define TH 32
#define IW 74                     // TW + 10
#define IH 42                     // TH + 10
#define HROW 66
#define PLW (IH * HROW)           // 2772 floats per hh plane
#define SM_FLOATS (2 * IH * IW + 4 * PLW)   // 6216 + 11088 = 17304
#define SM_BYTES (SM_FLOATS * 4)            // 69216
#define NPIX (16LL * 3 * 512 * 512)
#define GRID_X 8
#define GRID_Y 16
#define GRID_Z 48
#define GRID_TOTAL (GRID_X * GRID_Y * GRID_Z)

typedef unsigned long long u64;

__device__ double g_sum;
__device__ unsigned int g_count;

// Gaussian(sigma=1.5, K=11) weights, normalized — compile-time constants.
#define WV0 0.00102838f
#define WV1 0.00759876f
#define WV2 0.03600077f
#define WV3 0.10936069f
#define WV4 0.21300553f
#define WV5 0.26601172f

__device__ __forceinline__ u64 pack2(float lo, float hi) {
    u64 r; asm("mov.b64 %0,{%1,%2};" : "=l"(r) : "f"(lo), "f"(hi)); return r;
}
__device__ __forceinline__ void unpack2(u64 v, float& lo, float& hi) {
    asm("mov.b64 {%0,%1},%2;" : "=f"(lo), "=f"(hi) : "l"(v));
}
__device__ __forceinline__ u64 fma2(u64 a, u64 b, u64 c) {
    u64 d; asm("fma.rn.f32x2 %0,%1,%2,%3;" : "=l"(d) : "l"(a), "l"(b), "l"(c)); return d;
}
__device__ __forceinline__ u64 mul2(u64 a, u64 b) {
    u64 d; asm("mul.rn.f32x2 %0,%1,%2;" : "=l"(d) : "l"(a), "l"(b)); return d;
}
__device__ __forceinline__ u64 add2(u64 a, u64 b) {
    u64 d; asm("add.rn.f32x2 %0,%1,%2;" : "=l"(d) : "l"(a), "l"(b)); return d;
}
__device__ __forceinline__ u64 sub2(u64 a, u64 b) {
    u64 d; asm("sub.rn.f32x2 %0,%1,%2;" : "=l"(d) : "l"(a), "l"(b)); return d;
}

__global__ __launch_bounds__(256, 3) void ssim_kernel(
    const float* __restrict__ A, const float* __restrict__ B,
    float* __restrict__ out)
{
    extern __shared__ __align__(16) float sm[];
    float* sAf = sm;                          // IH*IW
    float* sBf = sm + IH * IW;                // IH*IW
    float* hhf = sm + 2 * IH * IW;            // 4 planes: A, B, A^2+B^2, AB
    __shared__ float wsum[8];

    const int tid = threadIdx.x;
    const int plane = blockIdx.z;
    const int tx0 = blockIdx.x * TW;
    const int ty0 = blockIdx.y * TH;
    const float* a = A + (size_t)plane * IMG * IMG + (ty0 - 5) * IMG + (tx0 - 5);
    const float* b = B + (size_t)plane * IMG * IMG + (ty0 - 5) * IMG + (tx0 - 5);

    // ---- Stage haloed 42x74 tile, zero-padded. All LDGs issued before any
    //      STS (MLP=26). One division; incremental (r,c) thereafter. ----
    {
        float va[13], vb[13];
        int r = tid / IW;
        int c = tid - r * IW;                 // 256 = 3*74 + 34
        int rj[13], cj[13];
#pragma unroll
        for (int j = 0; j < 13; j++) {
            rj[j] = r; cj[j] = c;
            r += 3; c += 34;
            if (c >= IW) { c -= IW; r += 1; }
        }
#pragma unroll
        for (int j = 0; j < 13; j++) {
            int gy = ty0 - 5 + rj[j];
            int gx = tx0 - 5 + cj[j];
            bool ok = (rj[j] < IH) &&
                      (gy >= 0) && (gy < IMG) && (gx >= 0) && (gx < IMG);
            int o = rj[j] * IMG + cj[j];
            va[j] = 0.f; vb[j] = 0.f;
            if (ok) { va[j] = __ldg(a + o); vb[j] = __ldg(b + o); }
        }
#pragma unroll
        for (int j = 0; j < 13; j++) {
            if (rj[j] < IH) {
                int idx = rj[j] * IW + cj[j];
                sAf[idx] = va[j];
                sBf[idx] = vb[j];
            }
        }
    }
    __syncthreads();

    // Packed (duplicated) weights.
    const u64 W0p = pack2(WV0, WV0), W1p = pack2(WV1, WV1), W2p = pack2(WV2, WV2);
    const u64 W3p = pack2(WV3, WV3), W4p = pack2(WV4, WV4), W5p = pack2(WV5, WV5);

    auto wp = [&](int t) -> u64 {
        switch (t) {
            case 0: case 10: return W0p;
            case 1: case 9:  return W1p;
            case 2: case 8:  return W2p;
            case 3: case 7:  return W3p;
            case 4: case 6:  return W4p;
            default:         return W5p;
        }
    };

    // Even/odd aligned-pair horizontal 11-tap conv: 4 outputs per call.
    auto hplane = [&](const u64* q, float* dst) {
        u64 E2a = fma2(W0p, add2(q[0], q[5]),
                  fma2(W2p, add2(q[1], q[4]),
                  mul2(W4p, add2(q[2], q[3]))));
        u64 E2b = fma2(W0p, add2(q[1], q[6]),
                  fma2(W2p, add2(q[2], q[5]),
                  mul2(W4p, add2(q[3], q[4]))));
        u64 Oa  = fma2(W1p, add2(q[0], q[4]),
                  fma2(W3p, add2(q[1], q[3]), mul2(W5p, q[2])));
        u64 Ob  = fma2(W1p, add2(q[1], q[5]),
                  fma2(W3p, add2(q[2], q[4]), mul2(W5p, q[3])));
        u64 Oc  = fma2(W1p, add2(q[2], q[6]),
                  fma2(W3p, add2(q[3], q[5]), mul2(W5p, q[4])));
        float oal, oah, obl, obh, ocl, och;
        unpack2(Oa, oal, oah);
        unpack2(Ob, obl, obh);
        unpack2(Oc, ocl, och);
        *(u64*)(dst)     = add2(E2a, pack2(oah, obl));
        *(u64*)(dst + 2) = add2(E2b, pack2(obh, ocl));
    };

    // ---- Horizontal pass: 42 rows x 16 groups of 4 outputs (672 items).
    //      Two-buffer (qa/qb live): 14 LDS.64 per group, zero re-reads. ----
    auto hgroup = [&](int g) {
        int r = g >> 4;
        int c0 = (g & 15) << 2;
        const float* rowA = sAf + r * IW + c0;
        const float* rowB = sBf + r * IW + c0;
        float* dst = hhf + r * HROW + c0;
        u64 qa[7], qb[7];
#pragma unroll
        for (int j = 0; j < 7; j++) qa[j] = *(const u64*)(rowA + 2 * j);
#pragma unroll
        for (int j = 0; j < 7; j++) qb[j] = *(const u64*)(rowB + 2 * j);
        hplane(qa, dst);                                  // A
        hplane(qb, dst + PLW);                            // B
#pragma unroll
        for (int j = 0; j < 7; j++) {
            u64 ab = mul2(qa[j], qb[j]);
            qa[j] = fma2(qa[j], qa[j], mul2(qb[j], qb[j]));
            qb[j] = ab;
        }
        hplane(qa, dst + 2 * PLW);                        // A^2 + B^2
        hplane(qb, dst + 3 * PLW);                        // AB
    };
    hgroup(tid);
    hgroup(tid + 256);
    if (tid < IH * 16 - 512) hgroup(tid + 512);           // 160 threads
    __syncthreads();

    // ---- Vertical pass: ALL 256 threads, each 2 cols x 4 rows, single
    //      sweep over all 4 planes (perfectly balanced: 256*8 = 2048 px). ----
    const float C1 = 0.0001f;
    const float C2 = 0.0009f;
    float accf = 0.f;
    {
        int xp = tid & 31;        // column pair 0..31
        int rg = tid >> 5;        // row group 0..7 (4 rows each)
        const float* hp = hhf + (rg * 4) * HROW + 2 * xp;

        u64 zero = pack2(0.f, 0.f);
        u64 m1[4], m2[4], ss[4], e12[4];
#pragma unroll
        for (int i = 0; i < 4; i++) { m1[i] = m2[i] = ss[i] = e12[i] = zero; }

#pragma unroll
        for (int k = 0; k < 14; k++) {
            u64 L0 = *(const u64*)(hp + k * HROW);
            u64 L1 = *(const u64*)(hp + k * HROW + PLW);
            u64 L2 = *(const u64*)(hp + k * HROW + 2 * PLW);
            u64 L3 = *(const u64*)(hp + k * HROW + 3 * PLW);
#pragma unroll
            for (int i = 0; i < 4; i++) {
                int t = k - i;
                if (t >= 0 && t <= 10) {
                    u64 w = wp(t);
                    m1[i]  = fma2(w, L0, m1[i]);
                    m2[i]  = fma2(w, L1, m2[i]);
                    ss[i]  = fma2(w, L2, ss[i]);
                    e12[i] = fma2(w, L3, e12[i]);
                }
            }
        }

        const u64 c1p = pack2(C1, C1);
        const u64 c2p = pack2(C2, C2);
#pragma unroll
        for (int i = 0; i < 4; i++) {
            u64 m1s = mul2(m1[i], m1[i]);
            u64 m2s = mul2(m2[i], m2[i]);
            u64 m12 = mul2(m1[i], m2[i]);
            u64 mss = add2(m1s, m2s);
            u64 p2  = add2(m12, m12);
            u64 t2  = add2(e12[i], e12[i]);
            u64 n1  = add2(p2, c1p);
            u64 n2  = add2(sub2(t2, p2), c2p);
            u64 d1  = add2(mss, c1p);
            u64 d2  = add2(sub2(ss[i], mss), c2p);
            u64 num = mul2(n1, n2);
            u64 den = mul2(d1, d2);
            float nx, ny, dx, dy;
            unpack2(num, nx, ny);
            unpack2(den, dx, dy);
            accf += __fdividef(nx, dx) + __fdividef(ny, dy);
        }
    }

    // ---- Block reduction + single-pass finalize ----
#pragma unroll
    for (int off = 16; off > 0; off >>= 1)
        accf += __shfl_down_sync(0xffffffffu, accf, off);
    if ((tid & 31) == 0) wsum[tid >> 5] = accf;
    __syncthreads();
    if (tid == 0) {
        float bsum = 0.f;
#pragma unroll
        for (int i = 0; i < 8; i++) bsum += wsum[i];
        atomicAdd(&g_sum, (double)bsum);
        __threadfence();
        unsigned int cold = atomicAdd(&g_count, 1u);
        if (cold == GRID_TOTAL - 1) {
            __threadfence();
            double s = *((volatile double*)&g_sum);
            out[0] = (float)(s / (double)NPIX);
            g_sum = 0.0;
            g_count = 0u;
            __threadfence();
        }
    }
}

extern "C" void kernel_launch(void* const* d_in, const int* in_sizes, int n_in,
                              void* d_out, int out_size)
{
    const float* A = (const float*)d_in[0];
    const float* B = (const float*)d_in[1];
    float* out = (float*)d_out;

    // Opt-in to >48KB dynamic shared memory (idempotent, not an allocation).
    cudaFuncSetAttribute(ssim_kernel,
                         cudaFuncAttributeMaxDynamicSharedMemorySize, SM_BYTES);

    dim3 grid(GRID_X, GRID_Y, GRID_Z);
    ssim_kernel<<<grid, 256, SM_BYTES>>>(A, B, out);
}